// round 8
// baseline (speedup 1.0000x reference)
#include <cuda_runtime.h>
#include <math.h>

// Problem dims
#define Bk 64
#define Tk 256
#define Dk 512
#define Hk 1024
#define Gk 3072   // 3*H
#define Ok 64
#define BT 16384  // B*T

typedef unsigned long long ull;

// -------- device scratch (no allocation allowed; __device__ globals are the workaround)
__device__ float g_gates[(long)BT * Gk];     // [T][B][3H], row r = t*B + b   (201 MB)
__device__ float g_hs[(long)Tk * Bk * Hk];   // [T][B][H] hidden states       (64 MB)
__device__ float g_h0[Bk * Hk];              // zero initial hidden state
__device__ float g_ghp[4 * Bk * Gk];         // K-split partials [ks][B][3H]  (3 MB)

// -------- packed f32x2 helpers (Blackwell FFMA2: 2x fp32 FMA throughput, exact fp32)
__device__ __forceinline__ ull ffma2(ull a, ull b, ull c) {
  ull d;
  asm("fma.rn.f32x2 %0, %1, %2, %3;" : "=l"(d) : "l"(a), "l"(b), "l"(c));
  return d;
}
__device__ __forceinline__ ull pack2(float lo, float hi) {
  ull d; asm("mov.b64 %0, {%1, %2};" : "=l"(d) : "f"(lo), "f"(hi)); return d;
}
__device__ __forceinline__ float2 unpack2(ull v) {
  float2 r; asm("mov.b64 {%0, %1}, %2;" : "=f"(r.x), "=f"(r.y) : "l"(v)); return r;
}
__device__ __forceinline__ float sigmoidf_(float x) { return 1.0f / (1.0f + expf(-x)); }

// ============================================================================
// Kernel 0: zero the initial hidden state (d_out-independent, deterministic)
// ============================================================================
__global__ void zero_h0_kernel() {
  int i = blockIdx.x * blockDim.x + threadIdx.x;
  if (i < Bk * Hk) g_h0[i] = 0.0f;
}

// ============================================================================
// Kernel 1: gates_x[r][c] = dot(emb[tok(r)], W_ih[c]) + b_ih[c]
//   r = t*B + b,  tok(r) = x[b*T + t]
//   GEMM M=16384 N=3072 K=512; block tile 128x64x32, 256 thr, 8x4 micro (f32x2)
// ============================================================================
__global__ __launch_bounds__(256) void gates_kernel(
    const int* __restrict__ x, const float* __restrict__ emb,
    const float* __restrict__ W_ih, const float* __restrict__ b_ih) {
  __shared__ __align__(16) float Xs[32][128];
  __shared__ __align__(16) float Ws[32][64];
  __shared__ int toks[128];

  const int tid = threadIdx.x;
  const int r0 = blockIdx.x * 128;
  const int c0 = blockIdx.y * 64;

  if (tid < 128) {
    int r = r0 + tid;
    toks[tid] = x[(r & 63) * Tk + (r >> 6)];  // b = r&63, t = r>>6
  }
  __syncthreads();

  ull acc[4][4] = {};  // m-pairs (8 rows) x 4 cols
  const int m0 = (tid & 15) * 8;
  const int n0 = (tid >> 4) * 4;

  for (int kc = 0; kc < Dk; kc += 32) {
    // load X tile (transposed [k][m]) via gathered emb rows
#pragma unroll
    for (int i = 0; i < 4; i++) {
      int q = tid + i * 256;
      int m = q & 127, kq = q >> 7;
      float4 v = *reinterpret_cast<const float4*>(
          &emb[(long)toks[m] * Dk + kc + kq * 4]);
      Xs[kq * 4 + 0][m] = v.x; Xs[kq * 4 + 1][m] = v.y;
      Xs[kq * 4 + 2][m] = v.z; Xs[kq * 4 + 3][m] = v.w;
    }
    // load W tile (transposed [k][n])
#pragma unroll
    for (int i = 0; i < 2; i++) {
      int q = tid + i * 256;
      int n = q & 63, kq = q >> 6;
      float4 v = *reinterpret_cast<const float4*>(
          &W_ih[(long)(c0 + n) * Dk + kc + kq * 4]);
      Ws[kq * 4 + 0][n] = v.x; Ws[kq * 4 + 1][n] = v.y;
      Ws[kq * 4 + 2][n] = v.z; Ws[kq * 4 + 3][n] = v.w;
    }
    __syncthreads();

#pragma unroll
    for (int k = 0; k < 32; k++) {
      const ull* ap = reinterpret_cast<const ull*>(&Xs[k][m0]);
      ull av[4];
      av[0] = ap[0]; av[1] = ap[1]; av[2] = ap[2]; av[3] = ap[3];
      float4 bv = *reinterpret_cast<const float4*>(&Ws[k][n0]);
      ull bb[4];
      bb[0] = pack2(bv.x, bv.x); bb[1] = pack2(bv.y, bv.y);
      bb[2] = pack2(bv.z, bv.z); bb[3] = pack2(bv.w, bv.w);
#pragma unroll
      for (int i = 0; i < 4; i++)
#pragma unroll
        for (int j = 0; j < 4; j++)
          acc[i][j] = ffma2(av[i], bb[j], acc[i][j]);
    }
    __syncthreads();
  }

  const float bs0 = b_ih[c0 + n0 + 0], bs1 = b_ih[c0 + n0 + 1];
  const float bs2 = b_ih[c0 + n0 + 2], bs3 = b_ih[c0 + n0 + 3];
#pragma unroll
  for (int i = 0; i < 4; i++) {
    float2 u0 = unpack2(acc[i][0]), u1 = unpack2(acc[i][1]);
    float2 u2 = unpack2(acc[i][2]), u3 = unpack2(acc[i][3]);
    long rowa = (long)(r0 + m0 + 2 * i) * Gk + c0 + n0;
    float4 lo = make_float4(u0.x + bs0, u1.x + bs1, u2.x + bs2, u3.x + bs3);
    float4 hi = make_float4(u0.y + bs0, u1.y + bs1, u2.y + bs2, u3.y + bs3);
    *reinterpret_cast<float4*>(&g_gates[rowa]) = lo;
    *reinterpret_cast<float4*>(&g_gates[rowa + Gk]) = hi;
  }
}

// ============================================================================
// Kernel 2 (per step): partial gh = h_{t-1} @ W_hhᵀ, K-split x4
//   grid (48, 4): 64-col tile x 256-K slice; block 64x64x256, 256 thr, 4x4 micro
// ============================================================================
__global__ __launch_bounds__(256) void step_gemm(const float* __restrict__ W_hh, int t) {
  __shared__ __align__(16) float Hs[32][64];
  __shared__ __align__(16) float Ws[32][64];

  const float* __restrict__ h = (t == 0) ? g_h0 : (g_hs + (long)(t - 1) * Bk * Hk);
  const int tid = threadIdx.x;
  const int c0 = blockIdx.x * 64;
  const int k0 = blockIdx.y * 256;

  ull acc[2][4] = {};  // m-pairs (4 batch rows) x 4 cols
  const int m0 = (tid & 15) * 4;
  const int n0 = (tid >> 4) * 4;

  for (int kc = 0; kc < 256; kc += 32) {
#pragma unroll
    for (int i = 0; i < 2; i++) {
      int q = tid + i * 256;
      int b = q & 63, kq = q >> 6;
      float4 v = *reinterpret_cast<const float4*>(&h[b * Hk + k0 + kc + kq * 4]);
      Hs[kq * 4 + 0][b] = v.x; Hs[kq * 4 + 1][b] = v.y;
      Hs[kq * 4 + 2][b] = v.z; Hs[kq * 4 + 3][b] = v.w;
      float4 w = *reinterpret_cast<const float4*>(
          &W_hh[(long)(c0 + b) * Hk + k0 + kc + kq * 4]);
      Ws[kq * 4 + 0][b] = w.x; Ws[kq * 4 + 1][b] = w.y;
      Ws[kq * 4 + 2][b] = w.z; Ws[kq * 4 + 3][b] = w.w;
    }
    __syncthreads();

#pragma unroll
    for (int k = 0; k < 32; k++) {
      const ull* ap = reinterpret_cast<const ull*>(&Hs[k][m0]);
      ull a0 = ap[0], a1 = ap[1];
      float4 bv = *reinterpret_cast<const float4*>(&Ws[k][n0]);
      ull bb[4];
      bb[0] = pack2(bv.x, bv.x); bb[1] = pack2(bv.y, bv.y);
      bb[2] = pack2(bv.z, bv.z); bb[3] = pack2(bv.w, bv.w);
#pragma unroll
      for (int j = 0; j < 4; j++) {
        acc[0][j] = ffma2(a0, bb[j], acc[0][j]);
        acc[1][j] = ffma2(a1, bb[j], acc[1][j]);
      }
    }
    __syncthreads();
  }

  float* gp = g_ghp + (long)blockIdx.y * (Bk * Gk);
#pragma unroll
  for (int i = 0; i < 2; i++) {
    float2 u0 = unpack2(acc[i][0]), u1 = unpack2(acc[i][1]);
    float2 u2 = unpack2(acc[i][2]), u3 = unpack2(acc[i][3]);
    int ba = m0 + 2 * i;
    float4 lo = make_float4(u0.x, u1.x, u2.x, u3.x);
    float4 hi = make_float4(u0.y, u1.y, u2.y, u3.y);
    *reinterpret_cast<float4*>(&gp[(long)ba * Gk + c0 + n0]) = lo;
    *reinterpret_cast<float4*>(&gp[(long)(ba + 1) * Gk + c0 + n0]) = hi;
  }
}

// ============================================================================
// Kernel 3 (per step): reduce partials + GRU gate nonlinearity -> h_t
// ============================================================================
__global__ __launch_bounds__(256) void step_elem(const float* __restrict__ b_hh, int t) {
  const int i = blockIdx.x * 256 + threadIdx.x;  // 65536 threads
  const int b = i >> 10;
  const int j = i & 1023;

  float hr = 0.0f, hz = 0.0f, hn = 0.0f;
#pragma unroll
  for (int s = 0; s < 4; s++) {
    const float* gp = g_ghp + (long)(s * Bk + b) * Gk + j;
    hr += gp[0];
    hz += gp[1024];
    hn += gp[2048];
  }

  const float* gx = g_gates + (long)(t * Bk + b) * Gk + j;
  float r = sigmoidf_(gx[0]    + hr + b_hh[j]);
  float z = sigmoidf_(gx[1024] + hz + b_hh[j + 1024]);
  float n = tanhf(gx[2048] + r * (hn + b_hh[j + 2048]));

  const float* hprev = (t == 0) ? g_h0 : (g_hs + (long)(t - 1) * Bk * Hk);
  float hnew = (1.0f - z) * n + z * hprev[i];
  g_hs[(long)t * Bk * Hk + i] = hnew;
}

// ============================================================================
// Kernel 4: logits = hs @ W_fcᵀ + b_fc; sigmoid; labels. One block per t.
//   out layout: proba [B][T][O] then labels [B][T][O]
//   CRITICAL: label = (computed fp32 proba > 0.5f), NOT (logit > 0) — the
//   reference rounds sigmoid to fp32 first; sigmoid(tiny positive x) rounds
//   to exactly 0.5f (expf(-x) rounds to 1.0f), giving label 0 for logit > 0.
// ============================================================================
__global__ __launch_bounds__(256) void fc_kernel(const float* __restrict__ W_fc,
                                                 const float* __restrict__ b_fc,
                                                 float* __restrict__ out,
                                                 int write_labels) {
  __shared__ __align__(16) float Hs[32][64];
  __shared__ __align__(16) float Ws[32][64];

  const int t = blockIdx.x;
  const int tid = threadIdx.x;
  const float* __restrict__ hb = g_hs + (long)t * Bk * Hk;

  ull acc[2][4] = {};
  const int m0 = (tid & 15) * 4;   // batch rows
  const int n0 = (tid >> 4) * 4;   // output cols

  for (int kc = 0; kc < Hk; kc += 32) {
#pragma unroll
    for (int i = 0; i < 2; i++) {
      int q = tid + i * 256;
      int b = q & 63, kq = q >> 6;
      float4 v = *reinterpret_cast<const float4*>(&hb[b * Hk + kc + kq * 4]);
      Hs[kq * 4 + 0][b] = v.x; Hs[kq * 4 + 1][b] = v.y;
      Hs[kq * 4 + 2][b] = v.z; Hs[kq * 4 + 3][b] = v.w;
      float4 w = *reinterpret_cast<const float4*>(&W_fc[(long)b * Hk + kc + kq * 4]);
      Ws[kq * 4 + 0][b] = w.x; Ws[kq * 4 + 1][b] = w.y;
      Ws[kq * 4 + 2][b] = w.z; Ws[kq * 4 + 3][b] = w.w;
    }
    __syncthreads();

#pragma unroll
    for (int k = 0; k < 32; k++) {
      const ull* ap = reinterpret_cast<const ull*>(&Hs[k][m0]);
      ull a0 = ap[0], a1 = ap[1];
      float4 bv = *reinterpret_cast<const float4*>(&Ws[k][n0]);
      ull bb[4];
      bb[0] = pack2(bv.x, bv.x); bb[1] = pack2(bv.y, bv.y);
      bb[2] = pack2(bv.z, bv.z); bb[3] = pack2(bv.w, bv.w);
#pragma unroll
      for (int j = 0; j < 4; j++) {
        acc[0][j] = ffma2(a0, bb[j], acc[0][j]);
        acc[1][j] = ffma2(a1, bb[j], acc[1][j]);
      }
    }
    __syncthreads();
  }

  const float bs0 = b_fc[n0 + 0], bs1 = b_fc[n0 + 1];
  const float bs2 = b_fc[n0 + 2], bs3 = b_fc[n0 + 3];
#pragma unroll
  for (int i = 0; i < 2; i++) {
    float2 u0 = unpack2(acc[i][0]), u1 = unpack2(acc[i][1]);
    float2 u2 = unpack2(acc[i][2]), u3 = unpack2(acc[i][3]);
    float lg[2][4] = {
        {u0.x + bs0, u1.x + bs1, u2.x + bs2, u3.x + bs3},
        {u0.y + bs0, u1.y + bs1, u2.y + bs2, u3.y + bs3}};
#pragma unroll
    for (int p = 0; p < 2; p++) {
      int b = m0 + 2 * i + p;
      long base = ((long)b * Tk + t) * Ok + n0;
      float4 pr = make_float4(sigmoidf_(lg[p][0]), sigmoidf_(lg[p][1]),
                              sigmoidf_(lg[p][2]), sigmoidf_(lg[p][3]));
      *reinterpret_cast<float4*>(&out[base]) = pr;
      if (write_labels) {
        // label derived from the ROUNDED fp32 proba (matches reference exactly)
        float4 lb = make_float4(pr.x > 0.5f ? 1.0f : 0.0f,
                                pr.y > 0.5f ? 1.0f : 0.0f,
                                pr.z > 0.5f ? 1.0f : 0.0f,
                                pr.w > 0.5f ? 1.0f : 0.0f);
        *reinterpret_cast<float4*>(&out[(long)BT * Ok + base]) = lb;
      }
    }
  }
}

// ============================================================================
// Launch: graph-capturable (kernel launches only, deterministic, no allocs)
// ============================================================================
extern "C" void kernel_launch(void* const* d_in, const int* in_sizes, int n_in,
                              void* d_out, int out_size) {
  const int*   x    = (const int*)d_in[0];
  const float* emb  = (const float*)d_in[1];
  const float* W_ih = (const float*)d_in[2];
  const float* W_hh = (const float*)d_in[3];
  const float* b_ih = (const float*)d_in[4];
  const float* b_hh = (const float*)d_in[5];
  const float* W_fc = (const float*)d_in[6];
  const float* b_fc = (const float*)d_in[7];
  float* out = (float*)d_out;

  zero_h0_kernel<<<64, 1024>>>();

  // gates_x = gather(emb, x) @ W_ih^T + b_ih   [16384 x 3072]
  gates_kernel<<<dim3(128, 48), 256>>>(x, emb, W_ih, b_ih);

  // sequential GRU recurrence
  for (int t = 0; t < Tk; t++) {
    step_gemm<<<dim3(48, 4), 256>>>(W_hh, t);
    step_elem<<<256, 256>>>(b_hh, t);
  }

  const int write_labels = (out_size >= 2 * BT * Ok) ? 1 : 0;
  fc_kernel<<<256, 256>>>(W_fc, b_fc, out, write_labels);
}

// round 9
// speedup vs baseline: 1.2341x; 1.2341x over previous
#include <cuda_runtime.h>
#include <math.h>

// Problem dims
#define Bk 64
#define Tk 256
#define Dk 512
#define Hk 1024
#define Gk 3072   // 3*H
#define Ok 64
#define BT 16384  // B*T

#define NB 128        // persistent blocks: 32 col-groups x 4 K-splits (1/SM, <=148)
#define HSTR 68       // padded smem stride for transposed h tile (bank spread)

typedef unsigned long long ull;

// -------- device scratch (no allocation allowed; __device__ globals are the workaround)
__device__ float g_gates[(long)BT * Gk];     // [T][B][3H]   (201 MB)
__device__ float g_hs[(long)Tk * Bk * Hk];   // [T][B][H]    (64 MB)
__device__ float g_ghp[4 * Bk * Gk];         // K-split partials [s][B][3H] (3 MB)

__device__ unsigned g_bar_count;             // zero-init; returns to 0 every barrier
__device__ volatile unsigned g_bar_gen;      // monotonic generation counter

// -------- packed f32x2 helpers (Blackwell FFMA2: 2x fp32 FMA throughput, exact fp32)
__device__ __forceinline__ ull ffma2(ull a, ull b, ull c) {
  ull d;
  asm("fma.rn.f32x2 %0, %1, %2, %3;" : "=l"(d) : "l"(a), "l"(b), "l"(c));
  return d;
}
__device__ __forceinline__ ull pack2(float lo, float hi) {
  ull d; asm("mov.b64 %0, {%1, %2};" : "=l"(d) : "f"(lo), "f"(hi)); return d;
}
__device__ __forceinline__ float2 unpack2(ull v) {
  float2 r; asm("mov.b64 {%0, %1}, %2;" : "=f"(r.x), "=f"(r.y) : "l"(v)); return r;
}
__device__ __forceinline__ float sigmoidf_(float x) { return 1.0f / (1.0f + expf(-x)); }

// ============================================================================
// Kernel 1: gates_x = gather(emb, x) @ W_ih^T + b_ih   (M=16384 N=3072 K=512)
//   block tile 128x64x32, 256 thr, 8x4 micro. B pre-duplicated in smem as
//   f32x2 pairs so the inner loop is pure LDS.128 + FFMA2 (no pack movs).
//   Accumulation order identical to the previously passing kernel.
// ============================================================================
__global__ __launch_bounds__(256) void gates_kernel(
    const int* __restrict__ x, const float* __restrict__ emb,
    const float* __restrict__ W_ih, const float* __restrict__ b_ih) {
  __shared__ __align__(16) float Xs[32][128];
  __shared__ __align__(16) ull Wsd[32][64];
  __shared__ int toks[128];

  const int tid = threadIdx.x;
  const int r0 = blockIdx.x * 128;
  const int c0 = blockIdx.y * 64;

  if (tid < 128) {
    int r = r0 + tid;
    toks[tid] = x[(r & 63) * Tk + (r >> 6)];  // b = r&63, t = r>>6
  }
  __syncthreads();

  ull acc[4][4] = {};  // m-pairs (8 rows) x 4 cols
  const int m0 = (tid & 15) * 8;
  const int n0 = (tid >> 4) * 4;

  for (int kc = 0; kc < Dk; kc += 32) {
#pragma unroll
    for (int i = 0; i < 4; i++) {
      int q = tid + i * 256;
      int m = q & 127, kq = q >> 7;
      float4 v = *reinterpret_cast<const float4*>(
          &emb[(long)toks[m] * Dk + kc + kq * 4]);
      Xs[kq * 4 + 0][m] = v.x; Xs[kq * 4 + 1][m] = v.y;
      Xs[kq * 4 + 2][m] = v.z; Xs[kq * 4 + 3][m] = v.w;
    }
#pragma unroll
    for (int i = 0; i < 2; i++) {
      int q = tid + i * 256;
      int n = q & 63, kq = q >> 6;
      float4 v = *reinterpret_cast<const float4*>(
          &W_ih[(long)(c0 + n) * Dk + kc + kq * 4]);
      Wsd[kq * 4 + 0][n] = pack2(v.x, v.x);
      Wsd[kq * 4 + 1][n] = pack2(v.y, v.y);
      Wsd[kq * 4 + 2][n] = pack2(v.z, v.z);
      Wsd[kq * 4 + 3][n] = pack2(v.w, v.w);
    }
    __syncthreads();

#pragma unroll
    for (int k = 0; k < 32; k++) {
      const ull* ap = reinterpret_cast<const ull*>(&Xs[k][m0]);
      ull av[4];
      av[0] = ap[0]; av[1] = ap[1]; av[2] = ap[2]; av[3] = ap[3];
      const ull* bp = &Wsd[k][n0];
      ull bb[4];
      bb[0] = bp[0]; bb[1] = bp[1]; bb[2] = bp[2]; bb[3] = bp[3];
#pragma unroll
      for (int i = 0; i < 4; i++)
#pragma unroll
        for (int j = 0; j < 4; j++)
          acc[i][j] = ffma2(av[i], bb[j], acc[i][j]);
    }
    __syncthreads();
  }

  const float bs0 = b_ih[c0 + n0 + 0], bs1 = b_ih[c0 + n0 + 1];
  const float bs2 = b_ih[c0 + n0 + 2], bs3 = b_ih[c0 + n0 + 3];
#pragma unroll
  for (int i = 0; i < 4; i++) {
    float2 u0 = unpack2(acc[i][0]), u1 = unpack2(acc[i][1]);
    float2 u2 = unpack2(acc[i][2]), u3 = unpack2(acc[i][3]);
    long rowa = (long)(r0 + m0 + 2 * i) * Gk + c0 + n0;
    float4 lo = make_float4(u0.x + bs0, u1.x + bs1, u2.x + bs2, u3.x + bs3);
    float4 hi = make_float4(u0.y + bs0, u1.y + bs1, u2.y + bs2, u3.y + bs3);
    *reinterpret_cast<float4*>(&g_gates[rowa]) = lo;
    *reinterpret_cast<float4*>(&g_gates[rowa + Gk]) = hi;
  }
}

// ============================================================================
// Grid-wide spin barrier (all NB blocks guaranteed co-resident: 1 block/SM
// by smem footprint, NB=128 <= 148 SMs, nothing else running in-stream).
// ============================================================================
__device__ __forceinline__ void grid_bar() {
  __threadfence();       // make this thread's global stores visible pre-arrive
  __syncthreads();
  if (threadIdx.x == 0) {
    unsigned my = g_bar_gen;
    if (atomicAdd(&g_bar_count, 1u) == NB - 1) {
      g_bar_count = 0;
      __threadfence();
      g_bar_gen = my + 1;
    } else {
      while (g_bar_gen == my) { }
      __threadfence();
    }
  }
  __syncthreads();
}

// ============================================================================
// Persistent GRU recurrence: all 256 steps in ONE kernel.
//   Block (g = blk>>2, s = blk&3): owns H-cols [g*32, g*32+32) for all 3 gates
//   (96 W rows) and K slice [s*256, s*256+256). W slice stays in smem (96 KB).
//   Per step: fill transposed h tile -> GEMM partial -> bar -> reduce+gates
//   -> bar. FP accumulation order is bit-identical to the previous
//   step_gemm/step_elem pair (same K-split boundaries, ascending-k chains,
//   same reduce order) so label behavior is preserved exactly.
// ============================================================================
__global__ __launch_bounds__(256) void gru_persistent(
    const float* __restrict__ W_hh, const float* __restrict__ b_hh) {
  extern __shared__ float smem[];
  float* Ws = smem;                  // [256 k][96 rows]   96 KB
  float* Hs = smem + 256 * 96;       // [256 k][HSTR]      68 KB

  const int tid = threadIdx.x;
  const int g = blockIdx.x >> 2;     // 0..31 column group
  const int s = blockIdx.x & 3;      // 0..3  K split
  const int k0 = s * 256;

  // ---- load W slice once: smem row L (0..95): gate e=L>>5, local col c=L&31
  for (int q = tid; q < 96 * 64; q += 256) {
    int row = q >> 6;
    int f4 = q & 63;
    int e = row >> 5, c = row & 31;
    float4 v = *reinterpret_cast<const float4*>(
        &W_hh[(long)(e * Hk + g * 32 + c) * Hk + k0 + f4 * 4]);
    int kk = f4 * 4;
    Ws[(kk + 0) * 96 + row] = v.x;
    Ws[(kk + 1) * 96 + row] = v.y;
    Ws[(kk + 2) * 96 + row] = v.z;
    Ws[(kk + 3) * 96 + row] = v.w;
  }
  __syncthreads();

  const int m0 = (tid & 15) << 2;    // 4 batch rows
  const int n0 = (tid >> 4) * 6;     // 6 local cols = 3 f32x2 pairs
  const int hb = tid >> 2;           // h-fill: row
  const int hf = tid & 3;            //         float4 sub-index
  const int gtid = blockIdx.x * 256 + tid;  // 0..32767 for reduce stage

  for (int t = 0; t < Tk; t++) {
    if (t > 0) {
      // ---- fill transposed h tile: Hs[k][b] = h_{t-1}[b][k0+k]
      const float4* hrow = reinterpret_cast<const float4*>(
          &g_hs[(long)(t - 1) * (Bk * Hk) + hb * Hk + k0]);
#pragma unroll
      for (int i = 0; i < 16; i++) {
        int f4 = i * 4 + hf;
        float4 v = hrow[f4];
        int kk = f4 * 4;
        Hs[(kk + 0) * HSTR + hb] = v.x;
        Hs[(kk + 1) * HSTR + hb] = v.y;
        Hs[(kk + 2) * HSTR + hb] = v.z;
        Hs[(kk + 3) * HSTR + hb] = v.w;
      }
      __syncthreads();

      // ---- GEMM partial: [64 b x 96 cols x 256 k], pairs over N
      ull acc[4][3] = {};
#pragma unroll 4
      for (int k = 0; k < 256; k++) {
        float4 av = *reinterpret_cast<const float4*>(&Hs[k * HSTR + m0]);
        const float* wr = &Ws[k * 96 + n0];
        ull b0 = *reinterpret_cast<const ull*>(wr);
        ull b1 = *reinterpret_cast<const ull*>(wr + 2);
        ull b2 = *reinterpret_cast<const ull*>(wr + 4);
        ull a0 = pack2(av.x, av.x), a1 = pack2(av.y, av.y);
        ull a2 = pack2(av.z, av.z), a3 = pack2(av.w, av.w);
        acc[0][0] = ffma2(a0, b0, acc[0][0]);
        acc[0][1] = ffma2(a0, b1, acc[0][1]);
        acc[0][2] = ffma2(a0, b2, acc[0][2]);
        acc[1][0] = ffma2(a1, b0, acc[1][0]);
        acc[1][1] = ffma2(a1, b1, acc[1][1]);
        acc[1][2] = ffma2(a1, b2, acc[1][2]);
        acc[2][0] = ffma2(a2, b0, acc[2][0]);
        acc[2][1] = ffma2(a2, b1, acc[2][1]);
        acc[2][2] = ffma2(a2, b2, acc[2][2]);
        acc[3][0] = ffma2(a3, b0, acc[3][0]);
        acc[3][1] = ffma2(a3, b1, acc[3][1]);
        acc[3][2] = ffma2(a3, b2, acc[3][2]);
      }

      // ---- store partials into g_ghp[s][b][gatecol]
#pragma unroll
      for (int i = 0; i < 4; i++) {
        long rb = (long)(s * Bk + m0 + i) * Gk;
#pragma unroll
        for (int p = 0; p < 3; p++) {
          float2 u = unpack2(acc[i][p]);
          int L = n0 + 2 * p;                       // local col (even)
          int col = (L >> 5) * Hk + g * 32 + (L & 31);
          *reinterpret_cast<float2*>(&g_ghp[rb + col]) = u;
        }
      }
    }

    grid_bar();  // partials visible chip-wide

    // ---- reduce + gate nonlinearity (identical math/order to old step_elem)
#pragma unroll
    for (int r2 = 0; r2 < 2; r2++) {
      int i = gtid + r2 * 32768;
      int b = i >> 10, j = i & 1023;
      float hr = 0.0f, hz = 0.0f, hn = 0.0f;
      if (t > 0) {
#pragma unroll
        for (int ss = 0; ss < 4; ss++) {
          // __ldcg: these addresses repeat every step and L1 is not coherent
          // across SMs — must bypass L1 to avoid stale lines.
          const float* gp = g_ghp + (long)(ss * Bk + b) * Gk + j;
          hr += __ldcg(gp);
          hz += __ldcg(gp + 1024);
          hn += __ldcg(gp + 2048);
        }
      }
      const float* gx = g_gates + (long)(t * Bk + b) * Gk + j;
      float rr = sigmoidf_(gx[0]    + hr + b_hh[j]);
      float zz = sigmoidf_(gx[1024] + hz + b_hh[j + 1024]);
      float nn = tanhf(gx[2048] + rr * (hn + b_hh[j + 2048]));
      float hp = (t == 0) ? 0.0f : g_hs[(long)(t - 1) * (Bk * Hk) + i];
      g_hs[(long)t * (Bk * Hk) + i] = (1.0f - zz) * nn + zz * hp;
    }

    grid_bar();  // h(t) visible before next step's GEMM
  }
}

// ============================================================================
// Kernel 4: logits = hs @ W_fc^T + b_fc; sigmoid; labels. One block per t.
//   label = (computed fp32 proba > 0.5f) — matches reference rounding exactly.
// ============================================================================
__global__ __launch_bounds__(256) void fc_kernel(const float* __restrict__ W_fc,
                                                 const float* __restrict__ b_fc,
                                                 float* __restrict__ out,
                                                 int write_labels) {
  __shared__ __align__(16) float Hs[32][64];
  __shared__ __align__(16) float Ws[32][64];

  const int t = blockIdx.x;
  const int tid = threadIdx.x;
  const float* __restrict__ hb = g_hs + (long)t * Bk * Hk;

  ull acc[2][4] = {};
  const int m0 = (tid & 15) * 4;
  const int n0 = (tid >> 4) * 4;

  for (int kc = 0; kc < Hk; kc += 32) {
#pragma unroll
    for (int i = 0; i < 2; i++) {
      int q = tid + i * 256;
      int b = q & 63, kq = q >> 6;
      float4 v = *reinterpret_cast<const float4*>(&hb[b * Hk + kc + kq * 4]);
      Hs[kq * 4 + 0][b] = v.x; Hs[kq * 4 + 1][b] = v.y;
      Hs[kq * 4 + 2][b] = v.z; Hs[kq * 4 + 3][b] = v.w;
      float4 w = *reinterpret_cast<const float4*>(&W_fc[(long)b * Hk + kc + kq * 4]);
      Ws[kq * 4 + 0][b] = w.x; Ws[kq * 4 + 1][b] = w.y;
      Ws[kq * 4 + 2][b] = w.z; Ws[kq * 4 + 3][b] = w.w;
    }
    __syncthreads();

#pragma unroll
    for (int k = 0; k < 32; k++) {
      const ull* ap = reinterpret_cast<const ull*>(&Hs[k][m0]);
      ull a0 = ap[0], a1 = ap[1];
      float4 bv = *reinterpret_cast<const float4*>(&Ws[k][n0]);
      ull bb[4];
      bb[0] = pack2(bv.x, bv.x); bb[1] = pack2(bv.y, bv.y);
      bb[2] = pack2(bv.z, bv.z); bb[3] = pack2(bv.w, bv.w);
#pragma unroll
      for (int j = 0; j < 4; j++) {
        acc[0][j] = ffma2(a0, bb[j], acc[0][j]);
        acc[1][j] = ffma2(a1, bb[j], acc[1][j]);
      }
    }
    __syncthreads();
  }

  const float bs0 = b_fc[n0 + 0], bs1 = b_fc[n0 + 1];
  const float bs2 = b_fc[n0 + 2], bs3 = b_fc[n0 + 3];
#pragma unroll
  for (int i = 0; i < 2; i++) {
    float2 u0 = unpack2(acc[i][0]), u1 = unpack2(acc[i][1]);
    float2 u2 = unpack2(acc[i][2]), u3 = unpack2(acc[i][3]);
    float lg[2][4] = {
        {u0.x + bs0, u1.x + bs1, u2.x + bs2, u3.x + bs3},
        {u0.y + bs0, u1.y + bs1, u2.y + bs2, u3.y + bs3}};
#pragma unroll
    for (int p = 0; p < 2; p++) {
      int b = m0 + 2 * i + p;
      long base = ((long)b * Tk + t) * Ok + n0;
      float4 pr = make_float4(sigmoidf_(lg[p][0]), sigmoidf_(lg[p][1]),
                              sigmoidf_(lg[p][2]), sigmoidf_(lg[p][3]));
      *reinterpret_cast<float4*>(&out[base]) = pr;
      if (write_labels) {
        float4 lb = make_float4(pr.x > 0.5f ? 1.0f : 0.0f,
                                pr.y > 0.5f ? 1.0f : 0.0f,
                                pr.z > 0.5f ? 1.0f : 0.0f,
                                pr.w > 0.5f ? 1.0f : 0.0f);
        *reinterpret_cast<float4*>(&out[(long)BT * Ok + base]) = lb;
      }
    }
  }
}

// ============================================================================
// Launch: graph-capturable (kernel launches only, deterministic, no allocs)
// ============================================================================
extern "C" void kernel_launch(void* const* d_in, const int* in_sizes, int n_in,
                              void* d_out, int out_size) {
  const int*   x    = (const int*)d_in[0];
  const float* emb  = (const float*)d_in[1];
  const float* W_ih = (const float*)d_in[2];
  const float* W_hh = (const float*)d_in[3];
  const float* b_ih = (const float*)d_in[4];
  const float* b_hh = (const float*)d_in[5];
  const float* W_fc = (const float*)d_in[6];
  const float* b_fc = (const float*)d_in[7];
  float* out = (float*)d_out;

  const int smem_bytes = (256 * 96 + 256 * HSTR) * (int)sizeof(float);  // 164 KB
  cudaFuncSetAttribute(gru_persistent,
                       cudaFuncAttributeMaxDynamicSharedMemorySize, smem_bytes);

  gates_kernel<<<dim3(128, 48), 256>>>(x, emb, W_ih, b_ih);
  gru_persistent<<<NB, 256, smem_bytes>>>(W_hh, b_hh);

  const int write_labels = (out_size >= 2 * BT * Ok) ? 1 : 0;
  fc_kernel<<<256, 256>>>(W_fc, b_fc, out, write_labels);
}

// round 10
// speedup vs baseline: 1.9018x; 1.5411x over previous
#include <cuda_runtime.h>
#include <math.h>
#include <stdint.h>

// Problem dims
#define Bk 64
#define Tk 256
#define Dk 512
#define Hk 1024
#define Gk 3072   // 3*H
#define Ok 64
#define BT 16384  // B*T

#define NB 128    // persistent blocks, one per 8 h-columns; all co-resident (1/SM)

typedef unsigned long long ull;

// -------- device scratch (no allocation allowed; __device__ globals are the workaround)
__device__ float g_gates[(long)BT * Gk];      // [T][B][3H]  (201 MB)
__device__ float g_hsT[(long)Tk * Hk * Bk];   // [t][k][b] transposed h (64 MB)

__device__ unsigned g_bar_count;              // zero-init; returns to 0 every barrier
__device__ volatile unsigned g_bar_gen;       // monotonic generation counter

// -------- packed f32x2 helpers (Blackwell FFMA2: 2x fp32 FMA throughput, exact fp32)
__device__ __forceinline__ ull ffma2(ull a, ull b, ull c) {
  ull d;
  asm("fma.rn.f32x2 %0, %1, %2, %3;" : "=l"(d) : "l"(a), "l"(b), "l"(c));
  return d;
}
__device__ __forceinline__ ull pack2(float lo, float hi) {
  ull d; asm("mov.b64 %0, {%1, %2};" : "=l"(d) : "f"(lo), "f"(hi)); return d;
}
__device__ __forceinline__ float2 unpack2(ull v) {
  float2 r; asm("mov.b64 {%0, %1}, %2;" : "=f"(r.x), "=f"(r.y) : "l"(v)); return r;
}
__device__ __forceinline__ float sigmoidf_(float x) { return 1.0f / (1.0f + expf(-x)); }

// -------- cp.async (LDGSTS, L2 path: .cg avoids stale-L1 issues entirely)
__device__ __forceinline__ void cp16(uint32_t dst, const float* src) {
  asm volatile("cp.async.cg.shared.global [%0], [%1], 16;" :: "r"(dst), "l"(src));
}
__device__ __forceinline__ void cp_commit() { asm volatile("cp.async.commit_group;"); }
__device__ __forceinline__ void cp_wait0()  { asm volatile("cp.async.wait_group 0;"); }

// ============================================================================
// Kernel 1: gates_x = gather(emb, x) @ W_ih^T + b_ih   (M=16384 N=3072 K=512)
//   block tile 128x64x32, 256 thr. A pre-paired in smem as f32x2 of rows
//   (m, m+64) so inner A loads are 16-lane-consecutive LDS.64 (bank-conflict
//   free; the old (tid&15)*8 layout was 4-way conflicted -> fma was 28%).
//   Per-row k-chain order identical to the previously passing kernel.
// ============================================================================
__global__ __launch_bounds__(256) void gates_kernel(
    const int* __restrict__ x, const float* __restrict__ emb,
    const float* __restrict__ W_ih, const float* __restrict__ b_ih) {
  __shared__ __align__(16) ull Xsp[32][64];   // [k][pair j] = (row j, row j+64)
  __shared__ __align__(16) ull Wsd[32][64];   // [k][n] duplicated f32x2
  __shared__ int toks[128];

  const int tid = threadIdx.x;
  const int r0 = blockIdx.x * 128;
  const int c0 = blockIdx.y * 64;

  if (tid < 128) {
    int r = r0 + tid;
    toks[tid] = x[(r & 63) * Tk + (r >> 6)];  // b = r&63, t = r>>6
  }
  __syncthreads();

  ull acc[4][4] = {};  // 4 row-pairs x 4 cols
  const int l16 = tid & 15;
  const int n0 = (tid >> 4) * 4;

  const int jA = tid & 63;        // A fill: pair column
  const int kqA = tid >> 6;       //         k sub-range

  for (int kc = 0; kc < Dk; kc += 32) {
    // ---- fill A pairs: Xsp[k][j] = (emb[tok(j)][k], emb[tok(j+64)][k])
    const float* eb_lo = &emb[(long)toks[jA] * Dk + kc + kqA * 8];
    const float* eb_hi = &emb[(long)toks[jA + 64] * Dk + kc + kqA * 8];
#pragma unroll
    for (int u = 0; u < 2; u++) {
      float4 lo = *reinterpret_cast<const float4*>(eb_lo + u * 4);
      float4 hi = *reinterpret_cast<const float4*>(eb_hi + u * 4);
      int kk = kqA * 8 + u * 4;
      Xsp[kk + 0][jA] = pack2(lo.x, hi.x);
      Xsp[kk + 1][jA] = pack2(lo.y, hi.y);
      Xsp[kk + 2][jA] = pack2(lo.z, hi.z);
      Xsp[kk + 3][jA] = pack2(lo.w, hi.w);
    }
    // ---- fill B duplicated
#pragma unroll
    for (int i = 0; i < 2; i++) {
      int q = tid + i * 256;
      int n = q & 63, kq = q >> 6;
      float4 v = *reinterpret_cast<const float4*>(
          &W_ih[(long)(c0 + n) * Dk + kc + kq * 4]);
      Wsd[kq * 4 + 0][n] = pack2(v.x, v.x);
      Wsd[kq * 4 + 1][n] = pack2(v.y, v.y);
      Wsd[kq * 4 + 2][n] = pack2(v.z, v.z);
      Wsd[kq * 4 + 3][n] = pack2(v.w, v.w);
    }
    __syncthreads();

#pragma unroll
    for (int k = 0; k < 32; k++) {
      ull av[4];
#pragma unroll
      for (int i = 0; i < 4; i++) av[i] = Xsp[k][l16 + 16 * i];
      const ull* bp = &Wsd[k][n0];
      ull bb[4];
      bb[0] = bp[0]; bb[1] = bp[1]; bb[2] = bp[2]; bb[3] = bp[3];
#pragma unroll
      for (int i = 0; i < 4; i++)
#pragma unroll
        for (int j = 0; j < 4; j++)
          acc[i][j] = ffma2(av[i], bb[j], acc[i][j]);
    }
    __syncthreads();
  }

  const float bs0 = b_ih[c0 + n0 + 0], bs1 = b_ih[c0 + n0 + 1];
  const float bs2 = b_ih[c0 + n0 + 2], bs3 = b_ih[c0 + n0 + 3];
#pragma unroll
  for (int i = 0; i < 4; i++) {
    float2 u0 = unpack2(acc[i][0]), u1 = unpack2(acc[i][1]);
    float2 u2 = unpack2(acc[i][2]), u3 = unpack2(acc[i][3]);
    long rowa = (long)(r0 + l16 + 16 * i) * Gk + c0 + n0;  // lo half: row m
    float4 lo = make_float4(u0.x + bs0, u1.x + bs1, u2.x + bs2, u3.x + bs3);
    float4 hi = make_float4(u0.y + bs0, u1.y + bs1, u2.y + bs2, u3.y + bs3);
    *reinterpret_cast<float4*>(&g_gates[rowa]) = lo;
    *reinterpret_cast<float4*>(&g_gates[rowa + (long)64 * Gk]) = hi;  // hi: m+64
  }
}

// ============================================================================
// Grid-wide spin barrier (all NB blocks co-resident: 188KB smem -> 1 block/SM,
// NB=128 <= 148 SMs).
// ============================================================================
__device__ __forceinline__ void grid_bar() {
  __threadfence();
  __syncthreads();
  if (threadIdx.x == 0) {
    unsigned my = g_bar_gen;
    if (atomicAdd(&g_bar_count, 1u) == NB - 1) {
      g_bar_count = 0;
      __threadfence();
      g_bar_gen = my + 1;
    } else {
      while (g_bar_gen == my) { }
      __threadfence();
    }
  }
  __syncthreads();
}

// ============================================================================
// Persistent GRU recurrence, ONE grid barrier per step.
//   Block g owns h-cols [g*8, g*8+8) for all 3 gates (24 W rows), full K.
//   4 in-block k-quarter groups of 64 threads (k0 = q*256) reproduce the
//   exact 4-way K-split accumulation of the previously passing kernel; the
//   quarter partials reduce through SMEM (left fold s=0..3, identical).
//   h kept transposed in global ([t][k][b]) so the A fill is a raw contiguous
//   cp.async copy, double-buffered under the GEMM.
// ============================================================================
__global__ __launch_bounds__(256, 1) void gru_persistent(
    const float* __restrict__ W_hh, const float* __restrict__ b_hh) {
  extern __shared__ float smem[];
  float* Ws    = smem;                 // [1024 k][24 rows]          96 KB
  float* HsBuf = smem + 24576;         // [2 buf][4 q][32 k][64 b]   64 KB
  float* P     = HsBuf + 16384;        // [4 s][64 b][26 pad]        26 KB
  float* Hprev = P + 6656;             // [64 b][8 jl]                2 KB

  const int tid = threadIdx.x;
  const int g = blockIdx.x;            // 0..127: h-cols g*8..g*8+7
  const int q = tid >> 6;              // k-quarter 0..3
  const int l = tid & 63;
  const int m0 = (l & 15) << 2;        // 4 batch rows
  const int n0 = (l >> 4) * 6;         // 6 local cols = 3 f32x2 pairs
  const int jl = tid & 7;              // gate-stage: local h-col
  const int b0 = tid >> 3;             // gate-stage: batch (and b0+32)

  // ---- load W slice once: local row L = e*8+c  ->  W_hh row e*1024+g*8+c
  for (int i = tid; i < 24 * 256; i += 256) {
    int L = i >> 8;
    int f4 = i & 255;
    int e = L >> 3, c = L & 7;
    float4 v = *reinterpret_cast<const float4*>(
        &W_hh[(long)(e * Hk + g * 8 + c) * Hk + f4 * 4]);
    int kk = f4 * 4;
    Ws[(kk + 0) * 24 + L] = v.x;
    Ws[(kk + 1) * 24 + L] = v.y;
    Ws[(kk + 2) * 24 + L] = v.z;
    Ws[(kk + 3) * 24 + L] = v.w;
  }
  const float bh0 = b_hh[g * 8 + jl];
  const float bh1 = b_hh[Hk + g * 8 + jl];
  const float bh2 = b_hh[2 * Hk + g * 8 + jl];
  __syncthreads();

  const uint32_t hsbuf_s = (uint32_t)__cvta_generic_to_shared(HsBuf);

  for (int t = 0; t < Tk; t++) {
    // ---- prefetch gx for this step's gate stage (hides DRAM under the GEMM)
    float ga0, ga1, ga2, gb0, gb1, gb2;
    {
      const float* p0 = &g_gates[(long)(t * 64 + b0) * Gk + g * 8 + jl];
      ga0 = p0[0]; ga1 = p0[Hk]; ga2 = p0[2 * Hk];
      const float* p1 = &g_gates[(long)(t * 64 + b0 + 32) * Gk + g * 8 + jl];
      gb0 = p1[0]; gb1 = p1[Hk]; gb2 = p1[2 * Hk];
    }

    if (t > 0) {
      const float* src = g_hsT + (long)(t - 1) * (Hk * Bk) + q * 256 * 64;
      // prologue: chunk 0 -> buffer 0
      {
        uint32_t dst = hsbuf_s + (uint32_t)((0 * 4 + q) * 2048 + l * 4) * 4;
        const float* s0 = src + l * 4;
#pragma unroll
        for (int j = 0; j < 8; j++) cp16(dst + j * 1024, s0 + j * 256);
        cp_commit();
      }

      ull acc[4][3] = {};
#pragma unroll 1
      for (int i = 0; i < 8; i++) {
        cp_wait0();
        __syncthreads();   // chunk i resident; everyone done with prior GEMM
        if (i < 7) {       // prefetch chunk i+1 into the other buffer
          int bf = (i + 1) & 1;
          uint32_t dst = hsbuf_s + (uint32_t)((bf * 4 + q) * 2048 + l * 4) * 4;
          const float* s1 = src + (i + 1) * 2048 + l * 4;
#pragma unroll
          for (int j = 0; j < 8; j++) cp16(dst + j * 1024, s1 + j * 256);
          cp_commit();
        }
        const float* A = HsBuf + ((i & 1) * 4 + q) * 2048;
        const float* Bw = Ws + (q * 256 + i * 32) * 24;
#pragma unroll
        for (int kk = 0; kk < 32; kk++) {
          float4 av = *reinterpret_cast<const float4*>(&A[kk * 64 + m0]);
          const float* wr = &Bw[kk * 24 + n0];
          ull w0 = *reinterpret_cast<const ull*>(wr);
          ull w1 = *reinterpret_cast<const ull*>(wr + 2);
          ull w2 = *reinterpret_cast<const ull*>(wr + 4);
          ull a0 = pack2(av.x, av.x), a1 = pack2(av.y, av.y);
          ull a2 = pack2(av.z, av.z), a3 = pack2(av.w, av.w);
          acc[0][0] = ffma2(a0, w0, acc[0][0]);
          acc[0][1] = ffma2(a0, w1, acc[0][1]);
          acc[0][2] = ffma2(a0, w2, acc[0][2]);
          acc[1][0] = ffma2(a1, w0, acc[1][0]);
          acc[1][1] = ffma2(a1, w1, acc[1][1]);
          acc[1][2] = ffma2(a1, w2, acc[1][2]);
          acc[2][0] = ffma2(a2, w0, acc[2][0]);
          acc[2][1] = ffma2(a2, w1, acc[2][1]);
          acc[2][2] = ffma2(a2, w2, acc[2][2]);
          acc[3][0] = ffma2(a3, w0, acc[3][0]);
          acc[3][1] = ffma2(a3, w1, acc[3][1]);
          acc[3][2] = ffma2(a3, w2, acc[3][2]);
        }
      }

      // ---- quarter partials -> smem (stride 26: bank-spread, 8B aligned)
#pragma unroll
      for (int m = 0; m < 4; m++) {
        int bb = m0 + m;
        float* pp = &P[(q * 64 + bb) * 26 + n0];
#pragma unroll
        for (int p = 0; p < 3; p++)
          *reinterpret_cast<float2*>(pp + 2 * p) = unpack2(acc[m][p]);
      }
      __syncthreads();
    }

    // ---- gate stage: 2 outputs per thread (b0, jl) and (b0+32, jl)
#pragma unroll
    for (int r2 = 0; r2 < 2; r2++) {
      int bb = b0 + r2 * 32;
      float gx0 = r2 ? gb0 : ga0;
      float gx1 = r2 ? gb1 : ga1;
      float gx2 = r2 ? gb2 : ga2;
      float hr = 0.0f, hz = 0.0f, hn = 0.0f;
      if (t > 0) {
#pragma unroll
        for (int s = 0; s < 4; s++) {   // left fold s=0..3: identical order
          const float* pp = &P[(s * 64 + bb) * 26];
          hr += pp[jl];
          hz += pp[8 + jl];
          hn += pp[16 + jl];
        }
      }
      float rr = sigmoidf_(gx0 + hr + bh0);
      float zz = sigmoidf_(gx1 + hz + bh1);
      float nn = tanhf(gx2 + rr * (hn + bh2));
      float hp = (t == 0) ? 0.0f : Hprev[bb * 8 + jl];
      float hnew = (1.0f - zz) * nn + zz * hp;
      Hprev[bb * 8 + jl] = hnew;                               // own slot
      g_hsT[(long)t * (Hk * Bk) + (g * 8 + jl) * 64 + bb] = hnew;
    }

    grid_bar();  // h(t) visible chip-wide; also fences P reuse next step
  }
}

// ============================================================================
// Kernel 4: logits = hs @ W_fc^T + b_fc; sigmoid; labels. One block per t.
//   Reads transposed h. label = (computed fp32 proba > 0.5f) — matches the
//   reference's sigmoid-then-compare rounding exactly.
// ============================================================================
__global__ __launch_bounds__(256) void fc_kernel(const float* __restrict__ W_fc,
                                                 const float* __restrict__ b_fc,
                                                 float* __restrict__ out,
                                                 int write_labels) {
  __shared__ __align__(16) float Hs[32][64];
  __shared__ __align__(16) float Ws[32][64];

  const int t = blockIdx.x;
  const int tid = threadIdx.x;
  const float* __restrict__ hbT = g_hsT + (long)t * (Hk * Bk);

  ull acc[2][4] = {};
  const int m0 = (tid & 15) * 4;
  const int n0 = (tid >> 4) * 4;
  const int kr = tid >> 4, f4i = tid & 15;

  for (int kc = 0; kc < Hk; kc += 32) {
#pragma unroll
    for (int u = 0; u < 2; u++) {
      int kk = kr + u * 16;
      float4 v = *reinterpret_cast<const float4*>(&hbT[(long)(kc + kk) * 64 + f4i * 4]);
      *reinterpret_cast<float4*>(&Hs[kk][f4i * 4]) = v;
    }
#pragma unroll
    for (int i = 0; i < 2; i++) {
      int q = tid + i * 256;
      int b = q & 63, kq = q >> 6;
      float4 w = *reinterpret_cast<const float4*>(&W_fc[(long)b * Hk + kc + kq * 4]);
      Ws[kq * 4 + 0][b] = w.x; Ws[kq * 4 + 1][b] = w.y;
      Ws[kq * 4 + 2][b] = w.z; Ws[kq * 4 + 3][b] = w.w;
    }
    __syncthreads();

#pragma unroll
    for (int k = 0; k < 32; k++) {
      const ull* ap = reinterpret_cast<const ull*>(&Hs[k][m0]);
      ull a0 = ap[0], a1 = ap[1];
      float4 bv = *reinterpret_cast<const float4*>(&Ws[k][n0]);
      ull bb[4];
      bb[0] = pack2(bv.x, bv.x); bb[1] = pack2(bv.y, bv.y);
      bb[2] = pack2(bv.z, bv.z); bb[3] = pack2(bv.w, bv.w);
#pragma unroll
      for (int j = 0; j < 4; j++) {
        acc[0][j] = ffma2(a0, bb[j], acc[0][j]);
        acc[1][j] = ffma2(a1, bb[j], acc[1][j]);
      }
    }
    __syncthreads();
  }

  const float bs0 = b_fc[n0 + 0], bs1 = b_fc[n0 + 1];
  const float bs2 = b_fc[n0 + 2], bs3 = b_fc[n0 + 3];
#pragma unroll
  for (int i = 0; i < 2; i++) {
    float2 u0 = unpack2(acc[i][0]), u1 = unpack2(acc[i][1]);
    float2 u2 = unpack2(acc[i][2]), u3 = unpack2(acc[i][3]);
    float lg[2][4] = {
        {u0.x + bs0, u1.x + bs1, u2.x + bs2, u3.x + bs3},
        {u0.y + bs0, u1.y + bs1, u2.y + bs2, u3.y + bs3}};
#pragma unroll
    for (int p = 0; p < 2; p++) {
      int b = m0 + 2 * i + p;
      long base = ((long)b * Tk + t) * Ok + n0;
      float4 pr = make_float4(sigmoidf_(lg[p][0]), sigmoidf_(lg[p][1]),
                              sigmoidf_(lg[p][2]), sigmoidf_(lg[p][3]));
      *reinterpret_cast<float4*>(&out[base]) = pr;
      if (write_labels) {
        float4 lb = make_float4(pr.x > 0.5f ? 1.0f : 0.0f,
                                pr.y > 0.5f ? 1.0f : 0.0f,
                                pr.z > 0.5f ? 1.0f : 0.0f,
                                pr.w > 0.5f ? 1.0f : 0.0f);
        *reinterpret_cast<float4*>(&out[(long)BT * Ok + base]) = lb;
      }
    }
  }
}

// ============================================================================
// Launch: graph-capturable (kernel launches only, deterministic, no allocs)
// ============================================================================
extern "C" void kernel_launch(void* const* d_in, const int* in_sizes, int n_in,
                              void* d_out, int out_size) {
  const int*   x    = (const int*)d_in[0];
  const float* emb  = (const float*)d_in[1];
  const float* W_ih = (const float*)d_in[2];
  const float* W_hh = (const float*)d_in[3];
  const float* b_ih = (const float*)d_in[4];
  const float* b_hh = (const float*)d_in[5];
  const float* W_fc = (const float*)d_in[6];
  const float* b_fc = (const float*)d_in[7];
  float* out = (float*)d_out;

  const int smem_bytes = (24576 + 16384 + 6656 + 512) * (int)sizeof(float); // 188 KB
  cudaFuncSetAttribute(gru_persistent,
                       cudaFuncAttributeMaxDynamicSharedMemorySize, smem_bytes);

  gates_kernel<<<dim3(128, 48), 256>>>(x, emb, W_ih, b_ih);
  gru_persistent<<<NB, 256, smem_bytes>>>(W_hh, b_hh);

  const int write_labels = (out_size >= 2 * BT * Ok) ? 1 : 0;
  fc_kernel<<<256, 256>>>(W_fc, b_fc, out, write_labels);
}

// round 11
// speedup vs baseline: 2.0650x; 1.0858x over previous
#include <cuda_runtime.h>
#include <math.h>
#include <stdint.h>

// Problem dims
#define Bk 64
#define Tk 256
#define Dk 512
#define Hk 1024
#define Gk 3072   // 3*H
#define Ok 64
#define BT 16384  // B*T

#define NB 128    // persistent blocks, one per 8 h-columns; all co-resident (1/SM)

typedef unsigned long long ull;

// -------- device scratch (no allocation allowed; __device__ globals are the workaround)
__device__ float g_gates[(long)BT * Gk];      // [T][B][3H]  (201 MB)
__device__ float g_hsT[(long)Tk * Hk * Bk];   // [t][k][b] transposed h (64 MB)

__device__ unsigned g_bar_count;              // init barrier: returns to 0 each use
__device__ volatile unsigned g_bar_gen;       // init barrier: monotonic (replay-safe)
__device__ volatile unsigned g_flags[NB];     // flag barrier: per-block step count
__device__ volatile unsigned g_rel;           // flag barrier: release word

// -------- packed f32x2 helpers (Blackwell FFMA2: 2x fp32 FMA throughput, exact fp32)
__device__ __forceinline__ ull ffma2(ull a, ull b, ull c) {
  ull d;
  asm("fma.rn.f32x2 %0, %1, %2, %3;" : "=l"(d) : "l"(a), "l"(b), "l"(c));
  return d;
}
__device__ __forceinline__ ull pack2(float lo, float hi) {
  ull d; asm("mov.b64 %0, {%1, %2};" : "=l"(d) : "f"(lo), "f"(hi)); return d;
}
__device__ __forceinline__ float2 unpack2(ull v) {
  float2 r; asm("mov.b64 {%0, %1}, %2;" : "=f"(r.x), "=f"(r.y) : "l"(v)); return r;
}
__device__ __forceinline__ float sigmoidf_(float x) { return 1.0f / (1.0f + expf(-x)); }

// -------- cp.async (LDGSTS, L2 path: .cg avoids stale-L1 issues entirely)
__device__ __forceinline__ void cp16(uint32_t dst, const float* src) {
  asm volatile("cp.async.cg.shared.global [%0], [%1], 16;" :: "r"(dst), "l"(src));
}
__device__ __forceinline__ void cp_commit() { asm volatile("cp.async.commit_group;"); }
__device__ __forceinline__ void cp_wait0()  { asm volatile("cp.async.wait_group 0;"); }

// ============================================================================
// Kernel 1: gates_x = gather(emb, x) @ W_ih^T + b_ih   (M=16384 N=3072 K=512)
//   block tile 128x64x32, 256 thr. FILLS are warp-coalesced: each warp loads
//   4 rows x 8 float4 = 4 cache lines (old layout hit ~32 lines/warp -> L1tex
//   93%, fma 38%). A tile stored plain (padded stride 130); the micro-kernel
//   pairs ADJACENT rows via LDS.64 — each row keeps its own ascending-k FFMA
//   chain, so outputs are bit-identical to all previously passing versions.
// ============================================================================
__global__ __launch_bounds__(256) void gates_kernel(
    const int* __restrict__ x, const float* __restrict__ emb,
    const float* __restrict__ W_ih, const float* __restrict__ b_ih) {
  __shared__ __align__(16) float Xs[32 * 130];   // [k][row 0..127], stride 130
  __shared__ __align__(16) ull  Wsd[32 * 67];    // [k][n 0..63] dup f32x2, stride 67
  __shared__ int toks[128];

  const int tid = threadIdx.x;
  const int r0 = blockIdx.x * 128;
  const int c0 = blockIdx.y * 64;

  if (tid < 128) {
    int r = r0 + tid;
    toks[tid] = x[(r & 63) * Tk + (r >> 6)];  // b = r&63, t = r>>6
  }
  __syncthreads();

  ull acc[4][4] = {};                 // 4 adjacent-row pairs x 4 cols
  const int l16 = tid & 15;
  const int n0 = (tid >> 4) * 4;
  const int f4 = tid & 7;             // fill: float4 index within 32-float chunk
  const int rw = tid >> 3;            // fill: base row 0..31

  for (int kc = 0; kc < Dk; kc += 32) {
    // ---- A fill: 128 rows x 8 f4; per warp: 4 rows x 8 f4 = 4 lines
#pragma unroll
    for (int i = 0; i < 4; i++) {
      int row = rw + i * 32;
      float4 v = *reinterpret_cast<const float4*>(
          &emb[(long)toks[row] * Dk + kc + f4 * 4]);
      Xs[(f4 * 4 + 0) * 130 + row] = v.x;
      Xs[(f4 * 4 + 1) * 130 + row] = v.y;
      Xs[(f4 * 4 + 2) * 130 + row] = v.z;
      Xs[(f4 * 4 + 3) * 130 + row] = v.w;
    }
    // ---- W fill (duplicated f32x2): 64 rows x 8 f4; 4 lines/warp
#pragma unroll
    for (int i = 0; i < 2; i++) {
      int n = rw + i * 32;
      float4 v = *reinterpret_cast<const float4*>(
          &W_ih[(long)(c0 + n) * Dk + kc + f4 * 4]);
      Wsd[(f4 * 4 + 0) * 67 + n] = pack2(v.x, v.x);
      Wsd[(f4 * 4 + 1) * 67 + n] = pack2(v.y, v.y);
      Wsd[(f4 * 4 + 2) * 67 + n] = pack2(v.z, v.z);
      Wsd[(f4 * 4 + 3) * 67 + n] = pack2(v.w, v.w);
    }
    __syncthreads();

#pragma unroll
    for (int k = 0; k < 32; k++) {
      ull av[4];
#pragma unroll
      for (int i = 0; i < 4; i++)   // LDS.64: 16 lanes x consecutive 8B, no conflict
        av[i] = *reinterpret_cast<const ull*>(&Xs[k * 130 + 2 * (l16 + 16 * i)]);
      const ull* bp = &Wsd[k * 67 + n0];
      ull bb[4];
      bb[0] = bp[0]; bb[1] = bp[1]; bb[2] = bp[2]; bb[3] = bp[3];
#pragma unroll
      for (int i = 0; i < 4; i++)
#pragma unroll
        for (int j = 0; j < 4; j++)
          acc[i][j] = ffma2(av[i], bb[j], acc[i][j]);
    }
    __syncthreads();
  }

  const float bs0 = b_ih[c0 + n0 + 0], bs1 = b_ih[c0 + n0 + 1];
  const float bs2 = b_ih[c0 + n0 + 2], bs3 = b_ih[c0 + n0 + 3];
#pragma unroll
  for (int i = 0; i < 4; i++) {
    float2 u0 = unpack2(acc[i][0]), u1 = unpack2(acc[i][1]);
    float2 u2 = unpack2(acc[i][2]), u3 = unpack2(acc[i][3]);
    long rowa = (long)(r0 + 2 * (l16 + 16 * i)) * Gk + c0 + n0;   // lo: row 2m
    float4 lo = make_float4(u0.x + bs0, u1.x + bs1, u2.x + bs2, u3.x + bs3);
    float4 hi = make_float4(u0.y + bs0, u1.y + bs1, u2.y + bs2, u3.y + bs3);
    *reinterpret_cast<float4*>(&g_gates[rowa]) = lo;
    *reinterpret_cast<float4*>(&g_gates[rowa + Gk]) = hi;          // hi: row 2m+1
  }
}

// ============================================================================
// Barriers. init_bar: generation-relative atomic barrier (replay-safe), used
// ONCE at kernel entry to publish the flag resets. flag_bar: parallel STG
// arrivals (no 128-way atomic serialization), block 0 scans + releases.
// ============================================================================
__device__ __forceinline__ void init_bar() {
  __threadfence();
  __syncthreads();
  if (threadIdx.x == 0) {
    unsigned my = g_bar_gen;
    if (atomicAdd(&g_bar_count, 1u) == NB - 1) {
      g_bar_count = 0;
      __threadfence();
      g_bar_gen = my + 1;
    } else {
      while (g_bar_gen == my) { }
      __threadfence();
    }
  }
  __syncthreads();
}

__device__ __forceinline__ void flag_bar(unsigned s) {
  __syncthreads();                      // all block threads' writes precede leader
  if (blockIdx.x == 0) {
    if (threadIdx.x == 0) { __threadfence(); g_flags[0] = s; }
    if (threadIdx.x < NB) { while (g_flags[threadIdx.x] < s) { } }
    __syncthreads();
    if (threadIdx.x == 0) { __threadfence(); g_rel = s; }
    __syncthreads();
  } else {
    if (threadIdx.x == 0) {
      __threadfence();
      g_flags[blockIdx.x] = s;
      while (g_rel < s) { }
      __threadfence();
    }
    __syncthreads();
  }
}

// ============================================================================
// Persistent GRU recurrence, ONE grid barrier per step.
//   Block g owns h-cols [g*8, g*8+8) x 3 gates (24 W rows), full K. 4 in-block
//   k-quarter groups (k0 = q*256) reproduce the exact 4-way K-split chains;
//   quarter partials reduce through SMEM (left fold s=0..3). h transposed in
//   global ([t][k][b]); A fill is contiguous cp.async, double-buffered under
//   the GEMM. Accumulation order bit-identical to all passing versions.
// ============================================================================
__global__ __launch_bounds__(256, 1) void gru_persistent(
    const float* __restrict__ W_hh, const float* __restrict__ b_hh) {
  extern __shared__ float smem[];
  float* Ws    = smem;                 // [1024 k][24 rows]          96 KB
  float* HsBuf = smem + 24576;         // [2 buf][4 q][32 k][64 b]   64 KB
  float* P     = HsBuf + 16384;        // [4 s][64 b][26 pad]        26 KB
  float* Hprev = P + 6656;             // [64 b][8 jl]                2 KB

  const int tid = threadIdx.x;
  const int g = blockIdx.x;            // 0..127: h-cols g*8..g*8+7
  const int q = tid >> 6;              // k-quarter 0..3
  const int l = tid & 63;
  const int m0 = (l & 15) << 2;        // 4 batch rows
  const int n0 = (l >> 4) * 6;         // 6 local cols = 3 f32x2 pairs
  const int jl = tid & 7;              // gate-stage: local h-col
  const int b0 = tid >> 3;             // gate-stage: batch (and b0+32)

  // ---- reset flag-barrier state (persists across graph replays), publish it
  if (g == 0) {
    if (tid < NB) g_flags[tid] = 0;
    if (tid == 0) g_rel = 0;
  }

  // ---- load W slice once: local row L = e*8+c  ->  W_hh row e*1024+g*8+c
  for (int i = tid; i < 24 * 256; i += 256) {
    int L = i >> 8;
    int f4 = i & 255;
    int e = L >> 3, c = L & 7;
    float4 v = *reinterpret_cast<const float4*>(
        &W_hh[(long)(e * Hk + g * 8 + c) * Hk + f4 * 4]);
    int kk = f4 * 4;
    Ws[(kk + 0) * 24 + L] = v.x;
    Ws[(kk + 1) * 24 + L] = v.y;
    Ws[(kk + 2) * 24 + L] = v.z;
    Ws[(kk + 3) * 24 + L] = v.w;
  }
  const float bh0 = b_hh[g * 8 + jl];
  const float bh1 = b_hh[Hk + g * 8 + jl];
  const float bh2 = b_hh[2 * Hk + g * 8 + jl];

  init_bar();   // flag resets visible everywhere before any flag_bar arrival
  __syncthreads();

  const uint32_t hsbuf_s = (uint32_t)__cvta_generic_to_shared(HsBuf);

  for (int t = 0; t < Tk; t++) {
    // ---- prefetch gx for this step's gate stage (hidden under the GEMM)
    float ga0, ga1, ga2, gb0, gb1, gb2;
    {
      const float* p0 = &g_gates[(long)(t * 64 + b0) * Gk + g * 8 + jl];
      ga0 = p0[0]; ga1 = p0[Hk]; ga2 = p0[2 * Hk];
      const float* p1 = &g_gates[(long)(t * 64 + b0 + 32) * Gk + g * 8 + jl];
      gb0 = p1[0]; gb1 = p1[Hk]; gb2 = p1[2 * Hk];
    }

    if (t > 0) {
      const float* src = g_hsT + (long)(t - 1) * (Hk * Bk) + q * 256 * 64;
      {  // prologue: chunk 0 -> buffer 0
        uint32_t dst = hsbuf_s + (uint32_t)((0 * 4 + q) * 2048 + l * 4) * 4;
        const float* s0 = src + l * 4;
#pragma unroll
        for (int j = 0; j < 8; j++) cp16(dst + j * 1024, s0 + j * 256);
        cp_commit();
      }

      ull acc[4][3] = {};
#pragma unroll 1
      for (int i = 0; i < 8; i++) {
        cp_wait0();
        __syncthreads();   // chunk i resident; everyone done with prior GEMM
        if (i < 7) {       // prefetch chunk i+1 into the other buffer
          int bf = (i + 1) & 1;
          uint32_t dst = hsbuf_s + (uint32_t)((bf * 4 + q) * 2048 + l * 4) * 4;
          const float* s1 = src + (i + 1) * 2048 + l * 4;
#pragma unroll
          for (int j = 0; j < 8; j++) cp16(dst + j * 1024, s1 + j * 256);
          cp_commit();
        }
        const float* A = HsBuf + ((i & 1) * 4 + q) * 2048;
        const float* Bw = Ws + (q * 256 + i * 32) * 24;
#pragma unroll
        for (int kk = 0; kk < 32; kk++) {
          float4 av = *reinterpret_cast<const float4*>(&A[kk * 64 + m0]);
          const float* wr = &Bw[kk * 24 + n0];
          ull w0 = *reinterpret_cast<const ull*>(wr);
          ull w1 = *reinterpret_cast<const ull*>(wr + 2);
          ull w2 = *reinterpret_cast<const ull*>(wr + 4);
          ull a0 = pack2(av.x, av.x), a1 = pack2(av.y, av.y);
          ull a2 = pack2(av.z, av.z), a3 = pack2(av.w, av.w);
          acc[0][0] = ffma2(a0, w0, acc[0][0]);
          acc[0][1] = ffma2(a0, w1, acc[0][1]);
          acc[0][2] = ffma2(a0, w2, acc[0][2]);
          acc[1][0] = ffma2(a1, w0, acc[1][0]);
          acc[1][1] = ffma2(a1, w1, acc[1][1]);
          acc[1][2] = ffma2(a1, w2, acc[1][2]);
          acc[2][0] = ffma2(a2, w0, acc[2][0]);
          acc[2][1] = ffma2(a2, w1, acc[2][1]);
          acc[2][2] = ffma2(a2, w2, acc[2][2]);
          acc[3][0] = ffma2(a3, w0, acc[3][0]);
          acc[3][1] = ffma2(a3, w1, acc[3][1]);
          acc[3][2] = ffma2(a3, w2, acc[3][2]);
        }
      }

      // ---- quarter partials -> smem (stride 26: bank-spread, 8B aligned)
#pragma unroll
      for (int m = 0; m < 4; m++) {
        int bb = m0 + m;
        float* pp = &P[(q * 64 + bb) * 26 + n0];
#pragma unroll
        for (int p = 0; p < 3; p++)
          *reinterpret_cast<float2*>(pp + 2 * p) = unpack2(acc[m][p]);
      }
      __syncthreads();
    }

    // ---- gate stage: 2 outputs per thread (b0, jl) and (b0+32, jl)
#pragma unroll
    for (int r2 = 0; r2 < 2; r2++) {
      int bb = b0 + r2 * 32;
      float gx0 = r2 ? gb0 : ga0;
      float gx1 = r2 ? gb1 : ga1;
      float gx2 = r2 ? gb2 : ga2;
      float hr = 0.0f, hz = 0.0f, hn = 0.0f;
      if (t > 0) {
#pragma unroll
        for (int s = 0; s < 4; s++) {   // left fold s=0..3: identical order
          const float* pp = &P[(s * 64 + bb) * 26];
          hr += pp[jl];
          hz += pp[8 + jl];
          hn += pp[16 + jl];
        }
      }
      float rr = sigmoidf_(gx0 + hr + bh0);
      float zz = sigmoidf_(gx1 + hz + bh1);
      float nn = tanhf(gx2 + rr * (hn + bh2));
      float hp = (t == 0) ? 0.0f : Hprev[bb * 8 + jl];
      float hnew = (1.0f - zz) * nn + zz * hp;
      Hprev[bb * 8 + jl] = hnew;                               // own slot
      g_hsT[(long)t * (Hk * Bk) + (g * 8 + jl) * 64 + bb] = hnew;
    }

    flag_bar((unsigned)(t + 1));  // h(t) visible chip-wide; fences P reuse
  }
}

// ============================================================================
// Kernel 4: logits = hs @ W_fc^T + b_fc; sigmoid; labels. One block per t.
//   Reads transposed h. label = (computed fp32 proba > 0.5f) — matches the
//   reference's sigmoid-then-compare rounding exactly.
// ============================================================================
__global__ __launch_bounds__(256) void fc_kernel(const float* __restrict__ W_fc,
                                                 const float* __restrict__ b_fc,
                                                 float* __restrict__ out,
                                                 int write_labels) {
  __shared__ __align__(16) float Hs[32][64];
  __shared__ __align__(16) float Ws[32][64];

  const int t = blockIdx.x;
  const int tid = threadIdx.x;
  const float* __restrict__ hbT = g_hsT + (long)t * (Hk * Bk);

  ull acc[2][4] = {};
  const int m0 = (tid & 15) * 4;
  const int n0 = (tid >> 4) * 4;
  const int kr = tid >> 4, f4i = tid & 15;

  for (int kc = 0; kc < Hk; kc += 32) {
#pragma unroll
    for (int u = 0; u < 2; u++) {
      int kk = kr + u * 16;
      float4 v = *reinterpret_cast<const float4*>(&hbT[(long)(kc + kk) * 64 + f4i * 4]);
      *reinterpret_cast<float4*>(&Hs[kk][f4i * 4]) = v;
    }
#pragma unroll
    for (int i = 0; i < 2; i++) {
      int n = (tid >> 3) + i * 32;         // warp-coalesced: 4 rows x 8 f4
      int f4 = tid & 7;
      float4 w = *reinterpret_cast<const float4*>(&W_fc[(long)n * Hk + kc + f4 * 4]);
      Ws[f4 * 4 + 0][n] = w.x; Ws[f4 * 4 + 1][n] = w.y;
      Ws[f4 * 4 + 2][n] = w.z; Ws[f4 * 4 + 3][n] = w.w;
    }
    __syncthreads();

#pragma unroll
    for (int k = 0; k < 32; k++) {
      const ull* ap = reinterpret_cast<const ull*>(&Hs[k][m0]);
      ull a0 = ap[0], a1 = ap[1];
      float4 bv = *reinterpret_cast<const float4*>(&Ws[k][n0]);
      ull bb[4];
      bb[0] = pack2(bv.x, bv.x); bb[1] = pack2(bv.y, bv.y);
      bb[2] = pack2(bv.z, bv.z); bb[3] = pack2(bv.w, bv.w);
#pragma unroll
      for (int j = 0; j < 4; j++) {
        acc[0][j] = ffma2(a0, bb[j], acc[0][j]);
        acc[1][j] = ffma2(a1, bb[j], acc[1][j]);
      }
    }
    __syncthreads();
  }

  const float bs0 = b_fc[n0 + 0], bs1 = b_fc[n0 + 1];
  const float bs2 = b_fc[n0 + 2], bs3 = b_fc[n0 + 3];
#pragma unroll
  for (int i = 0; i < 2; i++) {
    float2 u0 = unpack2(acc[i][0]), u1 = unpack2(acc[i][1]);
    float2 u2 = unpack2(acc[i][2]), u3 = unpack2(acc[i][3]);
    float lg[2][4] = {
        {u0.x + bs0, u1.x + bs1, u2.x + bs2, u3.x + bs3},
        {u0.y + bs0, u1.y + bs1, u2.y + bs2, u3.y + bs3}};
#pragma unroll
    for (int p = 0; p < 2; p++) {
      int b = m0 + 2 * i + p;
      long base = ((long)b * Tk + t) * Ok + n0;
      float4 pr = make_float4(sigmoidf_(lg[p][0]), sigmoidf_(lg[p][1]),
                              sigmoidf_(lg[p][2]), sigmoidf_(lg[p][3]));
      *reinterpret_cast<float4*>(&out[base]) = pr;
      if (write_labels) {
        float4 lb = make_float4(pr.x > 0.5f ? 1.0f : 0.0f,
                                pr.y > 0.5f ? 1.0f : 0.0f,
                                pr.z > 0.5f ? 1.0f : 0.0f,
                                pr.w > 0.5f ? 1.0f : 0.0f);
        *reinterpret_cast<float4*>(&out[(long)BT * Ok + base]) = lb;
      }
    }
  }
}

// ============================================================================
// Launch: graph-capturable (kernel launches only, deterministic, no allocs)
// ============================================================================
extern "C" void kernel_launch(void* const* d_in, const int* in_sizes, int n_in,
                              void* d_out, int out_size) {
  const int*   x    = (const int*)d_in[0];
  const float* emb  = (const float*)d_in[1];
  const float* W_ih = (const float*)d_in[2];
  const float* W_hh = (const float*)d_in[3];
  const float* b_ih = (const float*)d_in[4];
  const float* b_hh = (const float*)d_in[5];
  const float* W_fc = (const float*)d_in[6];
  const float* b_fc = (const float*)d_in[7];
  float* out = (float*)d_out;

  const int smem_bytes = (24576 + 16384 + 6656 + 512) * (int)sizeof(float); // 188 KB
  cudaFuncSetAttribute(gru_persistent,
                       cudaFuncAttributeMaxDynamicSharedMemorySize, smem_bytes);

  gates_kernel<<<dim3(128, 48), 256>>>(x, emb, W_ih, b_ih);
  gru_persistent<<<NB, 256, smem_bytes>>>(W_hh, b_hh);

  const int write_labels = (out_size >= 2 * BT * Ok) ? 1 : 0;
  fc_kernel<<<256, 256>>>(W_fc, b_fc, out, write_labels);
}